// round 6
// baseline (speedup 1.0000x reference)
#include <cuda_runtime.h>

// Shapes (fixed):
//   W: [D=1024, ML=8192] row-major, b: [D=1024]
//   out: [B=4, S=4096, D=1024] = broadcast_B( W[:, :S].T + b )
#define B_DIM 4
#define S_DIM 4096
#define D_DIM 1024
#define ML_DIM 8192

#define TROW 33      // stride 33: STS bank=(4s4+k+drow)%32, LDS bank=(sl+4dg+j)%32, both CF
#define N_SUB 4      // 4 s-subtiles of 32 per CTA

// Persistent strip kernel: CTA = 32 d x 128 s, looped as 4 tiles of 32x32
// with double-buffered smem and 1-deep LDG prefetch. 1024 CTAs = one wave.
__global__ void __launch_bounds__(256)
posemb_v6(const float4* __restrict__ W4,
          const float4* __restrict__ bias4,
          float4* __restrict__ out4) {
    __shared__ float tile[2][32 * TROW];

    const int t  = threadIdx.x;
    const int s_base = blockIdx.x * (32 * N_SUB);
    const int d0     = blockIdx.y * 32;

    // producer mapping
    const int drow = t >> 3;   // 0..31 : d within tile
    const int s4   = t & 7;    // 0..7  : float4 index along s
    // consumer mapping
    const int sl = t >> 3;     // 0..31 : s within tile
    const int dg = t & 7;      // 0..7  : float4 group along d

    const float4 bb = __ldg(&bias4[(d0 >> 2) + dg]);

    const size_t wrow = (size_t)(d0 + drow) * (ML_DIM / 4) + (s_base >> 2) + s4;
    float4 w = __ldg(&W4[wrow]);          // prologue load, tile 0

    const size_t batch_stride = (size_t)S_DIM * (D_DIM / 4);
    const int sb = 4 * s4;

#pragma unroll
    for (int u = 0; u < N_SUB; u++) {
        float* buf = tile[u & 1];
        buf[(sb + 0) * TROW + drow] = w.x;
        buf[(sb + 1) * TROW + drow] = w.y;
        buf[(sb + 2) * TROW + drow] = w.z;
        buf[(sb + 3) * TROW + drow] = w.w;

        // prefetch next tile's W fragment (overlaps with bar + LDS + STG below)
        if (u + 1 < N_SUB) w = __ldg(&W4[wrow + 8 * (u + 1)]);

        __syncthreads();

        const float* row = &tile[u & 1][sl * TROW + 4 * dg];
        float4 v;
        v.x = row[0] + bb.x;
        v.y = row[1] + bb.y;
        v.z = row[2] + bb.z;
        v.w = row[3] + bb.w;

        const size_t base =
            (size_t)(s_base + 32 * u + sl) * (D_DIM / 4) + (d0 >> 2) + dg;
#pragma unroll
        for (int bbt = 0; bbt < B_DIM; bbt++) {
            out4[(size_t)bbt * batch_stride + base] = v;
        }
        // no trailing bar: double buffer + next iteration's bar protect reuse
    }
}

extern "C" void kernel_launch(void* const* d_in, const int* in_sizes, int n_in,
                              void* d_out, int out_size) {
    (void)in_sizes; (void)n_in; (void)out_size;
    const float4* W4    = (const float4*)d_in[1];
    const float4* bias4 = (const float4*)d_in[2];
    float4* out4        = (float4*)d_out;

    dim3 block(256);
    dim3 grid(S_DIM / (32 * N_SUB), D_DIM / 32);  // 32 x 32 = 1024 CTAs, one wave
    posemb_v6<<<grid, block>>>(W4, bias4, out4);
}